// round 2
// baseline (speedup 1.0000x reference)
#include <cuda_runtime.h>
#include <cstdint>

#define NB_CAT  8192
#define RANK    16
#define N_COLS  4

// out[p] = sum_c dot(cf[c, x[p,c], :16], cf[c, y[p,c], :16]) + (x[p,c]==y[p,c] ? std[c,x]^2 : 0)
//
// Layout: 4 lanes per pair (sub = lane&3 = float4 chunk of the 16-float row),
// 8 pairs per warp (unit = lane>>2). Columns iterated in-register: each lane
// accumulates its chunk's partial dot across all 4 columns, then a 2-shuffle
// reduction over the 4 chunk lanes produces the pair's result.
//
// Per 8 pairs: 2 int4 index loads (1 wf each), 8 table load instrs (8 wf each,
// 1 wf per 64B row = optimal), 2 SHFLs, 1 store wf. This cuts MIO/shuffle
// pressure 8x vs the column-per-lane layout.

__global__ __launch_bounds__(256) void pair_cov_kernel(
    const int*   __restrict__ x,
    const int*   __restrict__ y,
    const float* __restrict__ cf,     // [N_COLS, NB_CAT, RANK]
    const float* __restrict__ stdv,   // [N_COLS, NB_CAT]
    float*       __restrict__ out,
    int n_pairs)
{
    const int lane = threadIdx.x & 31;
    const int sub  = lane & 3;        // float4 chunk within a row
    const int unit = lane >> 2;       // pair slot within warp-iter (0..7)

    const int warp_global = (int)((blockIdx.x * blockDim.x + threadIdx.x) >> 5);
    const int nwarps      = (int)((gridDim.x * blockDim.x) >> 5);

    const float4* cf4 = (const float4*)cf;   // [N_COLS * NB_CAT * 4] float4s

    for (int base = warp_global * 8; base < n_pairs; base += nwarps * 8) {
        const int p = base + unit;   // base multiple of 8, n_pairs multiple of 8

        // Per-pair index vectors (streaming; consecutive pairs -> 1 line -> 1 wf)
        const int4 xi = __ldcg((const int4*)x + p);
        const int4 yi = __ldcg((const int4*)y + p);

        float acc = 0.0f;

        #pragma unroll
        for (int c = 0; c < N_COLS; c++) {
            const int xc = (c == 0) ? xi.x : (c == 1) ? xi.y : (c == 2) ? xi.z : xi.w;
            const int yc = (c == 0) ? yi.x : (c == 1) ? yi.y : (c == 2) ? yi.z : yi.w;

            // 4 lanes x float4 = one 64B row = one L1 wavefront per row
            const float4 a = cf4[(size_t)(c * NB_CAT + xc) * (RANK / 4) + sub];
            const float4 b = cf4[(size_t)(c * NB_CAT + yc) * (RANK / 4) + sub];

            acc += a.x * b.x + a.y * b.y + a.z * b.z + a.w * b.w;
        }

        // Diagonal term: lane `sub` owns column `sub` (rare: xi==yi ~ 1/8192)
        {
            const int xd = (sub == 0) ? xi.x : (sub == 1) ? xi.y : (sub == 2) ? xi.z : xi.w;
            const int yd = (sub == 0) ? yi.x : (sub == 1) ? yi.y : (sub == 2) ? yi.z : yi.w;
            if (xd == yd) {
                const float s = stdv[sub * NB_CAT + xd];
                acc += s * s;
            }
        }

        // Reduce over the 4 chunk lanes
        acc += __shfl_xor_sync(0xffffffffu, acc, 1);
        acc += __shfl_xor_sync(0xffffffffu, acc, 2);

        if (sub == 0) {
            out[p] = acc;   // 8 lanes/warp write 32 contiguous bytes -> 1 wf
        }
    }
}

extern "C" void kernel_launch(void* const* d_in, const int* in_sizes, int n_in,
                              void* d_out, int out_size)
{
    const int*   x    = (const int*)d_in[0];
    const int*   y    = (const int*)d_in[1];
    const float* cf   = (const float*)d_in[2];
    const float* stdv = (const float*)d_in[3];
    float*       out  = (float*)d_out;

    const int n_pairs = out_size;  // 1048576

    const int threads = 256;
    const int blocks  = 148 * 16;
    pair_cov_kernel<<<blocks, threads>>>(x, y, cf, stdv, out, n_pairs);
}

// round 3
// speedup vs baseline: 1.5420x; 1.5420x over previous
#include <cuda_runtime.h>
#include <cstdint>

#define NB_CAT  8192
#define RANK    16
#define N_COLS  4

// out[p] = sum_c dot(cf[c, x[p,c], :16], cf[c, y[p,c], :16]) + (x[p,c]==y[p,c] ? std[c,x]^2 : 0)
//
// 4 lanes per pair (sub = float4 chunk), 8 pairs per warp-iter, columns
// iterated in-register. Per 8 pairs: 2 int4 index loads, 8 table LDG.128
// (8 wavefronts each; 1 wf per 64B row = optimal), 2 SHFLs, 1 store wf.
//
// R3 changes vs R2: __launch_bounds__(256,8) caps regs at 32 so occupancy
// returns to 64 warps/SM (R2's 38 regs dropped it to 67% and regressed);
// single resident wave (1184 blocks) with grid-stride loop.

__global__ __launch_bounds__(256, 8) void pair_cov_kernel(
    const int*   __restrict__ x,
    const int*   __restrict__ y,
    const float* __restrict__ cf,     // [N_COLS, NB_CAT, RANK]
    const float* __restrict__ stdv,   // [N_COLS, NB_CAT]
    float*       __restrict__ out,
    int n_pairs)
{
    const int lane = threadIdx.x & 31;
    const int sub  = lane & 3;        // float4 chunk within a row
    const int unit = lane >> 2;       // pair slot within warp-iter (0..7)

    const int warp_global = (int)((blockIdx.x * blockDim.x + threadIdx.x) >> 5);
    const int nwarps      = (int)((gridDim.x * blockDim.x) >> 5);

    const float4* cf4 = (const float4*)cf;   // [N_COLS * NB_CAT * 4] float4s

    for (int base = warp_global * 8; base < n_pairs; base += nwarps * 8) {
        const int p = base + unit;   // base multiple of 8, n_pairs multiple of 8

        // Coalesced per-pair index vectors (1 wf each, streaming past L1)
        const int4 xi = __ldcg((const int4*)x + p);
        const int4 yi = __ldcg((const int4*)y + p);

        float acc = 0.0f;

        #pragma unroll
        for (int c = 0; c < N_COLS; c++) {
            const int xc = (c == 0) ? xi.x : (c == 1) ? xi.y : (c == 2) ? xi.z : xi.w;
            const int yc = (c == 0) ? yi.x : (c == 1) ? yi.y : (c == 2) ? yi.z : yi.w;

            // 4 lanes x float4 = one 64B row = one L1 wavefront per row
            const float4 a = cf4[(size_t)(c * NB_CAT + xc) * (RANK / 4) + sub];
            const float4 b = cf4[(size_t)(c * NB_CAT + yc) * (RANK / 4) + sub];

            acc += a.x * b.x;
            acc += a.y * b.y;
            acc += a.z * b.z;
            acc += a.w * b.w;
        }

        // Diagonal term: lane `sub` owns column `sub` (rare: xi==yi ~ 1/8192)
        {
            const int xd = (sub == 0) ? xi.x : (sub == 1) ? xi.y : (sub == 2) ? xi.z : xi.w;
            const int yd = (sub == 0) ? yi.x : (sub == 1) ? yi.y : (sub == 2) ? yi.z : yi.w;
            if (xd == yd) {
                const float s = stdv[sub * NB_CAT + xd];
                acc += s * s;
            }
        }

        // Reduce over the 4 chunk lanes
        acc += __shfl_xor_sync(0xffffffffu, acc, 1);
        acc += __shfl_xor_sync(0xffffffffu, acc, 2);

        if (sub == 0) {
            out[p] = acc;   // 8 lanes/warp write 32 contiguous bytes -> 1 wf
        }
    }
}

extern "C" void kernel_launch(void* const* d_in, const int* in_sizes, int n_in,
                              void* d_out, int out_size)
{
    const int*   x    = (const int*)d_in[0];
    const int*   y    = (const int*)d_in[1];
    const float* cf   = (const float*)d_in[2];
    const float* stdv = (const float*)d_in[3];
    float*       out  = (float*)d_out;

    const int n_pairs = out_size;  // 1048576

    // Single resident wave: 148 SMs x 8 blocks (launch_bounds guarantees 8/SM)
    const int threads = 256;
    const int blocks  = 148 * 8;
    pair_cov_kernel<<<blocks, threads>>>(x, y, cf, stdv, out, n_pairs);
}